// round 1
// baseline (speedup 1.0000x reference)
#include <cuda_runtime.h>
#include <cstdint>

// Problem constants: B=4096, D_in=D_out=1024, out = [4096, 3072] fp32
#define NB   4096
#define DDIM 1024
#define OLD  3072   // out row stride in floats

// Scratch (no allocations allowed)
__device__ float g_a2[NB];
__device__ float g_p2[NB];
__device__ unsigned long long g_best[NB];

// ---------------------------------------------------------------------------
// Reset packed (dist_bits<<32 | idx) argmin accumulators
// ---------------------------------------------------------------------------
__global__ void init_best_kernel() {
    int i = blockIdx.x * blockDim.x + threadIdx.x;
    if (i < NB) g_best[i] = ~0ull;
}

// ---------------------------------------------------------------------------
// Projection GEMM: out[:,z*1024 : z*1024+1024] = X_z @ W + b
// 128x128x8 tile, 256 threads, 8x8 per thread.
// ---------------------------------------------------------------------------
__global__ __launch_bounds__(256) void proj_kernel(
    const float* __restrict__ ax, const float* __restrict__ px,
    const float* __restrict__ W, const float* __restrict__ bias,
    float* __restrict__ out)
{
    __shared__ float As[8][128];
    __shared__ float Bs[8][128];

    const float* X = blockIdx.z ? px : ax;
    const int coloff = blockIdx.z ? DDIM : 0;
    const int bm = blockIdx.y * 128;
    const int bn = blockIdx.x * 128;
    const int tid = threadIdx.x;
    const int tx = tid & 15;
    const int ty = tid >> 4;

    // A-tile load map: 128 rows x 8 k  -> thread loads one float4
    const int ar = tid >> 1;
    const int ak = (tid & 1) * 4;
    // B-tile load map: 8 k-rows x 128 cols -> thread loads one float4
    const int bk = tid >> 5;
    const int bc = (tid & 31) * 4;

    float acc[8][8];
#pragma unroll
    for (int i = 0; i < 8; ++i)
#pragma unroll
        for (int j = 0; j < 8; ++j) acc[i][j] = 0.f;

    for (int k0 = 0; k0 < DDIM; k0 += 8) {
        float4 av = *reinterpret_cast<const float4*>(&X[(size_t)(bm + ar) * DDIM + k0 + ak]);
        float4 bv = *reinterpret_cast<const float4*>(&W[(size_t)(k0 + bk) * DDIM + bn + bc]);
        __syncthreads();
        As[ak + 0][ar] = av.x; As[ak + 1][ar] = av.y;
        As[ak + 2][ar] = av.z; As[ak + 3][ar] = av.w;
        *reinterpret_cast<float4*>(&Bs[bk][bc]) = bv;
        __syncthreads();
#pragma unroll
        for (int k = 0; k < 8; ++k) {
            float a[8], bb[8];
            *reinterpret_cast<float4*>(&a[0]) = *reinterpret_cast<const float4*>(&As[k][ty * 8]);
            *reinterpret_cast<float4*>(&a[4]) = *reinterpret_cast<const float4*>(&As[k][ty * 8 + 4]);
            *reinterpret_cast<float4*>(&bb[0]) = *reinterpret_cast<const float4*>(&Bs[k][tx * 8]);
            *reinterpret_cast<float4*>(&bb[4]) = *reinterpret_cast<const float4*>(&Bs[k][tx * 8 + 4]);
#pragma unroll
            for (int i = 0; i < 8; ++i)
#pragma unroll
                for (int j = 0; j < 8; ++j)
                    acc[i][j] = fmaf(a[i], bb[j], acc[i][j]);
        }
    }

    float bv8[8];
#pragma unroll
    for (int j = 0; j < 8; ++j) bv8[j] = bias[bn + tx * 8 + j];

#pragma unroll
    for (int i = 0; i < 8; ++i) {
        const int m = bm + ty * 8 + i;
        float* o = &out[(size_t)m * OLD + coloff + bn + tx * 8];
        float4 r0, r1;
        r0.x = acc[i][0] + bv8[0]; r0.y = acc[i][1] + bv8[1];
        r0.z = acc[i][2] + bv8[2]; r0.w = acc[i][3] + bv8[3];
        r1.x = acc[i][4] + bv8[4]; r1.y = acc[i][5] + bv8[5];
        r1.z = acc[i][6] + bv8[6]; r1.w = acc[i][7] + bv8[7];
        *reinterpret_cast<float4*>(o)     = r0;
        *reinterpret_cast<float4*>(o + 4) = r1;
    }
}

// ---------------------------------------------------------------------------
// Row squared norms of anchor (y=0) and pos (y=1), read from out
// ---------------------------------------------------------------------------
__global__ __launch_bounds__(256) void norms_kernel(const float* __restrict__ out) {
    const int row = blockIdx.x;
    const int which = blockIdx.y;
    const float4* p = reinterpret_cast<const float4*>(out + (size_t)row * OLD + which * DDIM);
    float4 v = p[threadIdx.x];
    float s = v.x * v.x + v.y * v.y + v.z * v.z + v.w * v.w;
#pragma unroll
    for (int off = 16; off > 0; off >>= 1)
        s += __shfl_down_sync(0xFFFFFFFFu, s, off);
    __shared__ float ws[8];
    const int lane = threadIdx.x & 31, warp = threadIdx.x >> 5;
    if (lane == 0) ws[warp] = s;
    __syncthreads();
    if (threadIdx.x < 8) {
        s = ws[threadIdx.x];
#pragma unroll
        for (int off = 4; off > 0; off >>= 1)
            s += __shfl_down_sync(0x000000FFu, s, off);
        if (threadIdx.x == 0) (which ? g_p2 : g_a2)[row] = s;
    }
}

// ---------------------------------------------------------------------------
// Dist GEMM + fused argmin: dist[i,j] = a2[i]+p2[j]-2*anchor_i.pos_j
// Packed (float_bits<<32 | j) atomicMin per row (deterministic).
// ---------------------------------------------------------------------------
__global__ __launch_bounds__(256) void dist_kernel(const float* __restrict__ out) {
    __shared__ float As[8][128];
    __shared__ float Bs[8][128];

    const int bm = blockIdx.y * 128;
    const int bn = blockIdx.x * 128;
    const int tid = threadIdx.x;
    const int tx = tid & 15;
    const int ty = tid >> 4;

    const int ar = tid >> 1;
    const int ak = (tid & 1) * 4;

    const float* A = out;          // anchor, ld = OLD
    const float* P = out + DDIM;   // pos,    ld = OLD

    float acc[8][8];
#pragma unroll
    for (int i = 0; i < 8; ++i)
#pragma unroll
        for (int j = 0; j < 8; ++j) acc[i][j] = 0.f;

    for (int k0 = 0; k0 < DDIM; k0 += 8) {
        float4 av = *reinterpret_cast<const float4*>(&A[(size_t)(bm + ar) * OLD + k0 + ak]);
        float4 pv = *reinterpret_cast<const float4*>(&P[(size_t)(bn + ar) * OLD + k0 + ak]);
        __syncthreads();
        As[ak + 0][ar] = av.x; As[ak + 1][ar] = av.y;
        As[ak + 2][ar] = av.z; As[ak + 3][ar] = av.w;
        Bs[ak + 0][ar] = pv.x; Bs[ak + 1][ar] = pv.y;
        Bs[ak + 2][ar] = pv.z; Bs[ak + 3][ar] = pv.w;
        __syncthreads();
#pragma unroll
        for (int k = 0; k < 8; ++k) {
            float a[8], bb[8];
            *reinterpret_cast<float4*>(&a[0]) = *reinterpret_cast<const float4*>(&As[k][ty * 8]);
            *reinterpret_cast<float4*>(&a[4]) = *reinterpret_cast<const float4*>(&As[k][ty * 8 + 4]);
            *reinterpret_cast<float4*>(&bb[0]) = *reinterpret_cast<const float4*>(&Bs[k][tx * 8]);
            *reinterpret_cast<float4*>(&bb[4]) = *reinterpret_cast<const float4*>(&Bs[k][tx * 8 + 4]);
#pragma unroll
            for (int i = 0; i < 8; ++i)
#pragma unroll
                for (int j = 0; j < 8; ++j)
                    acc[i][j] = fmaf(a[i], bb[j], acc[i][j]);
        }
    }

    float p2c[8];
#pragma unroll
    for (int j = 0; j < 8; ++j) p2c[j] = g_p2[bn + tx * 8 + j];

#pragma unroll
    for (int i = 0; i < 8; ++i) {
        const int m = bm + ty * 8 + i;
        const float a2v = g_a2[m];
        unsigned long long best = ~0ull;
#pragma unroll
        for (int j = 0; j < 8; ++j) {
            const int n = bn + tx * 8 + j;
            float dist = a2v + p2c[j] - 2.0f * acc[i][j];
            if (n == m) dist = 3.0e38f;  // mask diagonal
            unsigned long long pk =
                ((unsigned long long)__float_as_uint(dist) << 32) | (unsigned)n;
            best = (pk < best) ? pk : best;
        }
        // reduce across the 16 lanes (same ty) of the half-warp
#pragma unroll
        for (int off = 8; off > 0; off >>= 1) {
            unsigned long long o = __shfl_down_sync(0xFFFFFFFFu, best, off);
            best = (o < best) ? o : best;
        }
        if (tx == 0) atomicMin(&g_best[m], best);
    }
}

// ---------------------------------------------------------------------------
// Gather hard negatives: out[:, 2048:3072] = pos[argmin]
// ---------------------------------------------------------------------------
__global__ __launch_bounds__(256) void gather_kernel(float* __restrict__ out) {
    const int row = blockIdx.x;
    const int idx = (int)(unsigned)(g_best[row] & 0xFFFFFFFFull);
    const float4* src = reinterpret_cast<const float4*>(out + (size_t)idx * OLD + DDIM);
    float4* dst = reinterpret_cast<float4*>(out + (size_t)row * OLD + 2 * DDIM);
    dst[threadIdx.x] = src[threadIdx.x];
}

// ---------------------------------------------------------------------------
extern "C" void kernel_launch(void* const* d_in, const int* in_sizes, int n_in,
                              void* d_out, int out_size) {
    (void)in_sizes; (void)n_in; (void)out_size;
    const float* ax   = (const float*)d_in[0];
    const float* px   = (const float*)d_in[1];
    const float* W    = (const float*)d_in[2];
    const float* bias = (const float*)d_in[3];
    float* out = (float*)d_out;

    init_best_kernel<<<(NB + 255) / 256, 256>>>();
    proj_kernel<<<dim3(DDIM / 128, NB / 128, 2), 256>>>(ax, px, W, bias, out);
    norms_kernel<<<dim3(NB, 2), 256>>>(out);
    dist_kernel<<<dim3(NB / 128, NB / 128), 256>>>(out);
    gather_kernel<<<NB, 256>>>(out);
}

// round 4
// speedup vs baseline: 2.2449x; 2.2449x over previous
#include <cuda_runtime.h>
#include <cuda_bf16.h>
#include <cstdint>

#define NB   4096
#define DDIM 1024
#define OLD  3072

// ---------------- scratch globals (no allocs allowed) ----------------
__device__ __nv_bfloat16 g_abf[NB * DDIM];          // anchor bf16
__device__ __nv_bfloat16 g_pbf[NB * DDIM];          // pos bf16
__device__ float g_p2[NB];                          // ||pos||^2
__device__ float g_est[(size_t)NB * NB];            // estimated dist (64MB)
__device__ int   g_idx[NB];                         // final argmin

__device__ __forceinline__ uint32_t smem_u32(const void* p) {
    uint32_t a;
    asm("{ .reg .u64 t; cvta.to.shared.u64 t, %1; cvt.u32.u64 %0, t; }" : "=r"(a) : "l"(p));
    return a;
}
#define SWZ(o) ((uint32_t)(o) ^ ((((uint32_t)(o)) >> 3) & 0x70u))

// ---------------------------------------------------------------------------
// Projection GEMM (fp32): out[:, z*1024 : +1024] = X_z @ W + b, plus bf16 copy
// ---------------------------------------------------------------------------
__global__ __launch_bounds__(256) void proj_kernel(
    const float* __restrict__ ax, const float* __restrict__ px,
    const float* __restrict__ W, const float* __restrict__ bias,
    float* __restrict__ out)
{
    __shared__ float As[8][128];
    __shared__ float Bs[8][128];

    const float* X = blockIdx.z ? px : ax;
    __nv_bfloat16* bf = blockIdx.z ? g_pbf : g_abf;
    const int coloff = blockIdx.z ? DDIM : 0;
    const int bm = blockIdx.y * 128;
    const int bn = blockIdx.x * 128;
    const int tid = threadIdx.x;
    const int tx = tid & 15;
    const int ty = tid >> 4;
    const int ar = tid >> 1;
    const int ak = (tid & 1) * 4;
    const int bk = tid >> 5;
    const int bc = (tid & 31) * 4;

    float acc[8][8];
#pragma unroll
    for (int i = 0; i < 8; ++i)
#pragma unroll
        for (int j = 0; j < 8; ++j) acc[i][j] = 0.f;

    for (int k0 = 0; k0 < DDIM; k0 += 8) {
        float4 av = *reinterpret_cast<const float4*>(&X[(size_t)(bm + ar) * DDIM + k0 + ak]);
        float4 bv = *reinterpret_cast<const float4*>(&W[(size_t)(k0 + bk) * DDIM + bn + bc]);
        __syncthreads();
        As[ak + 0][ar] = av.x; As[ak + 1][ar] = av.y;
        As[ak + 2][ar] = av.z; As[ak + 3][ar] = av.w;
        *reinterpret_cast<float4*>(&Bs[bk][bc]) = bv;
        __syncthreads();
#pragma unroll
        for (int k = 0; k < 8; ++k) {
            float a[8], bb[8];
            *reinterpret_cast<float4*>(&a[0]) = *reinterpret_cast<const float4*>(&As[k][ty * 8]);
            *reinterpret_cast<float4*>(&a[4]) = *reinterpret_cast<const float4*>(&As[k][ty * 8 + 4]);
            *reinterpret_cast<float4*>(&bb[0]) = *reinterpret_cast<const float4*>(&Bs[k][tx * 8]);
            *reinterpret_cast<float4*>(&bb[4]) = *reinterpret_cast<const float4*>(&Bs[k][tx * 8 + 4]);
#pragma unroll
            for (int i = 0; i < 8; ++i)
#pragma unroll
                for (int j = 0; j < 8; ++j)
                    acc[i][j] = fmaf(a[i], bb[j], acc[i][j]);
        }
    }

    float bv8[8];
#pragma unroll
    for (int j = 0; j < 8; ++j) bv8[j] = bias[bn + tx * 8 + j];

#pragma unroll
    for (int i = 0; i < 8; ++i) {
        const int m = bm + ty * 8 + i;
        float v[8];
#pragma unroll
        for (int j = 0; j < 8; ++j) v[j] = acc[i][j] + bv8[j];
        float* o = &out[(size_t)m * OLD + coloff + bn + tx * 8];
        *reinterpret_cast<float4*>(o)     = make_float4(v[0], v[1], v[2], v[3]);
        *reinterpret_cast<float4*>(o + 4) = make_float4(v[4], v[5], v[6], v[7]);
        __nv_bfloat162 h0 = __floats2bfloat162_rn(v[0], v[1]);
        __nv_bfloat162 h1 = __floats2bfloat162_rn(v[2], v[3]);
        __nv_bfloat162 h2 = __floats2bfloat162_rn(v[4], v[5]);
        __nv_bfloat162 h3 = __floats2bfloat162_rn(v[6], v[7]);
        uint4 pk;
        pk.x = *reinterpret_cast<uint32_t*>(&h0);
        pk.y = *reinterpret_cast<uint32_t*>(&h1);
        pk.z = *reinterpret_cast<uint32_t*>(&h2);
        pk.w = *reinterpret_cast<uint32_t*>(&h3);
        *reinterpret_cast<uint4*>(&bf[(size_t)m * DDIM + bn + tx * 8]) = pk;
    }
}

// ---------------------------------------------------------------------------
// ||pos_row||^2
// ---------------------------------------------------------------------------
__global__ __launch_bounds__(256) void norms_kernel(const float* __restrict__ out) {
    const int row = blockIdx.x;
    const float4* p = reinterpret_cast<const float4*>(out + (size_t)row * OLD + DDIM);
    float4 v = p[threadIdx.x];
    float s = v.x * v.x + v.y * v.y + v.z * v.z + v.w * v.w;
#pragma unroll
    for (int off = 16; off > 0; off >>= 1) s += __shfl_down_sync(0xFFFFFFFFu, s, off);
    __shared__ float ws[8];
    const int lane = threadIdx.x & 31, warp = threadIdx.x >> 5;
    if (lane == 0) ws[warp] = s;
    __syncthreads();
    if (threadIdx.x == 0) {
        float t = 0.f;
#pragma unroll
        for (int w = 0; w < 8; ++w) t += ws[w];
        g_p2[row] = t;
    }
}

// ---------------------------------------------------------------------------
// Phase 1: bf16 mma.sync dist estimate. est[i,j] = p2[j] - 2*dot_bf16(a_i,p_j)
// 128x128 tile, BK=64, cp.async double-buffered, SW128-swizzled ldmatrix.
// B fragments loaded with NON-trans ldmatrix: smem is K-major [n][k], which is
// already the (k-consecutive, n=lane/4) orientation mma.row.col requires.
// ---------------------------------------------------------------------------
#define BK 64
#define TILE_BYTES (128 * 128)      // 16KB per operand tile (128 rows x 128B)
#define DSMEM_BYTES (4 * TILE_BYTES)

__device__ __forceinline__ void load_stage(uint32_t sA, uint32_t sB,
                                           int bm, int bn, int kc, int tid) {
#pragma unroll
    for (int it = 0; it < 4; ++it) {
        int idx = it * 256 + tid;
        int r = idx >> 3, c = idx & 7;
        uint32_t so = SWZ(r * 128 + c * 16);
        const void* srcA = &g_abf[(size_t)(bm + r) * DDIM + kc * BK + c * 8];
        asm volatile("cp.async.cg.shared.global [%0], [%1], 16;"
                     :: "r"(sA + so), "l"(srcA));
        const void* srcB = &g_pbf[(size_t)(bn + r) * DDIM + kc * BK + c * 8];
        asm volatile("cp.async.cg.shared.global [%0], [%1], 16;"
                     :: "r"(sB + so), "l"(srcB));
    }
}

__global__ __launch_bounds__(256) void dist_est_kernel() {
    extern __shared__ __align__(1024) char smem[];
    const uint32_t sb = smem_u32(smem);
    const int tid = threadIdx.x;
    const int wid = tid >> 5, lane = tid & 31;
    const int bm = blockIdx.y * 128;
    const int bn = blockIdx.x * 128;
    const int m_off = (wid & 3) * 32;
    const int n_off = (wid >> 2) * 64;

    const uint32_t sA[2] = {sb,                 sb + 2 * TILE_BYTES};
    const uint32_t sB[2] = {sb + TILE_BYTES,    sb + 3 * TILE_BYTES};

    float acc[2][8][4];
#pragma unroll
    for (int i = 0; i < 2; ++i)
#pragma unroll
        for (int j = 0; j < 8; ++j)
#pragma unroll
            for (int c = 0; c < 4; ++c) acc[i][j][c] = 0.f;

    load_stage(sA[0], sB[0], bm, bn, 0, tid);
    asm volatile("cp.async.commit_group;" ::: "memory");

    const int mi = lane >> 3;     // ldmatrix sub-matrix index
    const int mr = lane & 7;      // row within sub-matrix

    for (int kc = 0; kc < DDIM / BK; ++kc) {
        const int cur = kc & 1;
        if (kc + 1 < DDIM / BK) {
            load_stage(sA[cur ^ 1], sB[cur ^ 1], bm, bn, kc + 1, tid);
            asm volatile("cp.async.commit_group;" ::: "memory");
            asm volatile("cp.async.wait_group 1;" ::: "memory");
        } else {
            asm volatile("cp.async.wait_group 0;" ::: "memory");
        }
        __syncthreads();

#pragma unroll
        for (int ks = 0; ks < 4; ++ks) {
            uint32_t a[2][4];
#pragma unroll
            for (int i = 0; i < 2; ++i) {
                int row = m_off + i * 16 + ((mi & 1) << 3) + mr;
                int kb = ks * 32 + ((mi >> 1) << 4);
                uint32_t addr = sA[cur] + SWZ(row * 128 + kb);
                asm volatile(
                    "ldmatrix.sync.aligned.m8n8.x4.shared.b16 {%0,%1,%2,%3}, [%4];"
                    : "=r"(a[i][0]), "=r"(a[i][1]), "=r"(a[i][2]), "=r"(a[i][3])
                    : "r"(addr));
            }
            uint32_t b[4][4];
#pragma unroll
            for (int j2 = 0; j2 < 4; ++j2) {
                int row = n_off + j2 * 16 + ((mi >> 1) << 3) + mr;
                int kb = ks * 32 + ((mi & 1) << 4);
                uint32_t addr = sB[cur] + SWZ(row * 128 + kb);
                asm volatile(
                    "ldmatrix.sync.aligned.m8n8.x4.shared.b16 {%0,%1,%2,%3}, [%4];"
                    : "=r"(b[j2][0]), "=r"(b[j2][1]), "=r"(b[j2][2]), "=r"(b[j2][3])
                    : "r"(addr));
            }
#pragma unroll
            for (int i = 0; i < 2; ++i)
#pragma unroll
                for (int j = 0; j < 8; ++j) {
                    const uint32_t b0 = b[j >> 1][(j & 1) * 2];
                    const uint32_t b1 = b[j >> 1][(j & 1) * 2 + 1];
                    asm volatile(
                        "mma.sync.aligned.m16n8k16.row.col.f32.bf16.bf16.f32 "
                        "{%0,%1,%2,%3}, {%4,%5,%6,%7}, {%8,%9}, {%0,%1,%2,%3};"
                        : "+f"(acc[i][j][0]), "+f"(acc[i][j][1]),
                          "+f"(acc[i][j][2]), "+f"(acc[i][j][3])
                        : "r"(a[i][0]), "r"(a[i][1]), "r"(a[i][2]), "r"(a[i][3]),
                          "r"(b0), "r"(b1));
                }
        }
        __syncthreads();
    }

    // epilogue: est[m][n] = p2[n] - 2*dot; diagonal masked
    const int g = lane >> 2;
    const int c2 = (lane & 3) * 2;
#pragma unroll
    for (int i = 0; i < 2; ++i) {
#pragma unroll
        for (int j = 0; j < 8; ++j) {
            const int ncol = bn + n_off + j * 8 + c2;
            const float p2a = g_p2[ncol];
            const float p2b = g_p2[ncol + 1];
            const int r0 = bm + m_off + i * 16 + g;
            const int r1 = r0 + 8;
            float e00 = fmaf(-2.f, acc[i][j][0], p2a);
            float e01 = fmaf(-2.f, acc[i][j][1], p2b);
            float e10 = fmaf(-2.f, acc[i][j][2], p2a);
            float e11 = fmaf(-2.f, acc[i][j][3], p2b);
            if (ncol == r0) e00 = 3.0e38f;
            if (ncol + 1 == r0) e01 = 3.0e38f;
            if (ncol == r1) e10 = 3.0e38f;
            if (ncol + 1 == r1) e11 = 3.0e38f;
            *reinterpret_cast<float2*>(&g_est[(size_t)r0 * NB + ncol]) = make_float2(e00, e01);
            *reinterpret_cast<float2*>(&g_est[(size_t)r1 * NB + ncol]) = make_float2(e10, e11);
        }
    }
}

// ---------------------------------------------------------------------------
// Phase 2: per-row refine — exact fp32 distance on candidates within MARGIN.
// ---------------------------------------------------------------------------
#define MARGIN 4.0f

__global__ __launch_bounds__(256) void refine_kernel(const float* __restrict__ out) {
    const int row = blockIdx.x;
    const int tid = threadIdx.x;
    const int wid = tid >> 5, lid = tid & 31;
    const float* e = &g_est[(size_t)row * NB];

    __shared__ float red[8];
    __shared__ int   cand[64];
    __shared__ int   ccount;
    __shared__ float arow[DDIM];

    float lmin = 3.0e38f;
    for (int j = tid; j < NB; j += 256) lmin = fminf(lmin, e[j]);
#pragma unroll
    for (int off = 16; off > 0; off >>= 1)
        lmin = fminf(lmin, __shfl_xor_sync(0xFFFFFFFFu, lmin, off));
    if (lid == 0) red[wid] = lmin;
    if (tid == 0) ccount = 0;
    __syncthreads();
    float rowmin = red[0];
#pragma unroll
    for (int w = 1; w < 8; ++w) rowmin = fminf(rowmin, red[w]);

    const float thr = rowmin + MARGIN;
    for (int j = tid; j < NB; j += 256) {
        if (e[j] <= thr && j != row) {
            int p = atomicAdd(&ccount, 1);
            if (p < 64) cand[p] = j;
        }
    }
    for (int j = tid; j < DDIM; j += 256) arow[j] = out[(size_t)row * OLD + j];
    __syncthreads();

    int nc = ccount; if (nc > 64) nc = 64;
    unsigned long long best = ~0ull;
    for (int k = 0; k < nc; ++k) {
        const int j = cand[k];
        const float* prow = &out[(size_t)j * OLD + DDIM];
        float s = 0.f;
        for (int t = tid; t < DDIM; t += 256) s = fmaf(arow[t], prow[t], s);
#pragma unroll
        for (int off = 16; off > 0; off >>= 1) s += __shfl_xor_sync(0xFFFFFFFFu, s, off);
        if (lid == 0) red[wid] = s;
        __syncthreads();
        if (tid == 0) {
            float dot = 0.f;
#pragma unroll
            for (int w = 0; w < 8; ++w) dot += red[w];
            float dist = fmaf(-2.0f, dot, g_p2[j]);
            unsigned long long pk =
                ((unsigned long long)__float_as_uint(dist) << 32) | (unsigned)j;
            if (pk < best) best = pk;
        }
        __syncthreads();
    }
    if (tid == 0) g_idx[row] = (int)(unsigned)(best & 0xFFFFFFFFull);
}

// ---------------------------------------------------------------------------
// Gather hard negatives: out[:, 2048:3072] = pos[argmin]
// ---------------------------------------------------------------------------
__global__ __launch_bounds__(256) void gather_kernel(float* __restrict__ out) {
    const int row = blockIdx.x;
    const int idx = g_idx[row];
    const float4* src = reinterpret_cast<const float4*>(out + (size_t)idx * OLD + DDIM);
    float4* dst = reinterpret_cast<float4*>(out + (size_t)row * OLD + 2 * DDIM);
    dst[threadIdx.x] = src[threadIdx.x];
}

// ---------------------------------------------------------------------------
extern "C" void kernel_launch(void* const* d_in, const int* in_sizes, int n_in,
                              void* d_out, int out_size) {
    (void)in_sizes; (void)n_in; (void)out_size;
    const float* ax   = (const float*)d_in[0];
    const float* px   = (const float*)d_in[1];
    const float* W    = (const float*)d_in[2];
    const float* bias = (const float*)d_in[3];
    float* out = (float*)d_out;

    cudaFuncSetAttribute(dist_est_kernel,
                         cudaFuncAttributeMaxDynamicSharedMemorySize, DSMEM_BYTES);

    proj_kernel<<<dim3(DDIM / 128, NB / 128, 2), 256>>>(ax, px, W, bias, out);
    norms_kernel<<<NB, 256>>>(out);
    dist_est_kernel<<<dim3(NB / 128, NB / 128), 256, DSMEM_BYTES>>>();
    refine_kernel<<<NB, 256>>>(out);
    gather_kernel<<<NB, 256>>>(out);
}

// round 5
// speedup vs baseline: 4.5254x; 2.0158x over previous
#include <cuda_runtime.h>
#include <cuda_bf16.h>
#include <cuda_fp16.h>
#include <cstdint>

#define NB   4096
#define DDIM 1024
#define OLD  3072

// ---------------- scratch globals (no allocs allowed) ----------------
__device__ __nv_bfloat16 g_xhi[2ull * NB * DDIM];   // input splits (anchor,pos)
__device__ __nv_bfloat16 g_xlo[2ull * NB * DDIM];
__device__ __nv_bfloat16 g_whi[DDIM * DDIM];        // W transposed [n][k], hi
__device__ __nv_bfloat16 g_wlo[DDIM * DDIM];        // W transposed [n][k], lo
__device__ __nv_bfloat16 g_abf[NB * DDIM];          // anchor output bf16
__device__ __nv_bfloat16 g_pbf[NB * DDIM];          // pos output bf16
__device__ float  g_p2[NB];                         // ||pos||^2
__device__ __half g_est[(size_t)NB * NB];           // estimated dist (32MB)
__device__ int    g_idx[NB];                        // final argmin

__device__ __forceinline__ uint32_t smem_u32(const void* p) {
    uint32_t a;
    asm("{ .reg .u64 t; cvta.to.shared.u64 t, %1; cvt.u32.u64 %0, t; }" : "=r"(a) : "l"(p));
    return a;
}
#define SWZ(o) ((uint32_t)(o) ^ ((((uint32_t)(o)) >> 3) & 0x70u))

// ---------------------------------------------------------------------------
// Split inputs into bf16 hi/lo. 8 floats per thread.
// ---------------------------------------------------------------------------
__global__ __launch_bounds__(256) void split_x_kernel(
    const float* __restrict__ ax, const float* __restrict__ px)
{
    const float* X = blockIdx.y ? px : ax;
    __nv_bfloat16* hi = g_xhi + (size_t)blockIdx.y * NB * DDIM;
    __nv_bfloat16* lo = g_xlo + (size_t)blockIdx.y * NB * DDIM;
    const size_t base = ((size_t)blockIdx.x * 256 + threadIdx.x) * 8;
    float4 v0 = *reinterpret_cast<const float4*>(X + base);
    float4 v1 = *reinterpret_cast<const float4*>(X + base + 4);
    float f[8] = {v0.x, v0.y, v0.z, v0.w, v1.x, v1.y, v1.z, v1.w};
    __align__(16) __nv_bfloat16 h[8], l[8];
#pragma unroll
    for (int i = 0; i < 8; ++i) {
        h[i] = __float2bfloat16(f[i]);
        l[i] = __float2bfloat16(f[i] - __bfloat162float(h[i]));
    }
    *reinterpret_cast<uint4*>(hi + base) = *reinterpret_cast<uint4*>(h);
    *reinterpret_cast<uint4*>(lo + base) = *reinterpret_cast<uint4*>(l);
}

// ---------------------------------------------------------------------------
// Transpose + split W: g_whi/g_wlo[n][k] = split(W[k][n])
// ---------------------------------------------------------------------------
__global__ __launch_bounds__(256) void split_w_kernel(const float* __restrict__ W) {
    __shared__ float t[32][33];
    const int k0 = blockIdx.y * 32, n0 = blockIdx.x * 32;
    const int tx = threadIdx.x & 31, ty = threadIdx.x >> 5;  // 32x8
#pragma unroll
    for (int i = 0; i < 4; ++i)
        t[ty + i * 8][tx] = W[(size_t)(k0 + ty + i * 8) * DDIM + n0 + tx];
    __syncthreads();
#pragma unroll
    for (int i = 0; i < 4; ++i) {
        const int n = n0 + ty + i * 8;
        const float v = t[tx][ty + i * 8];
        __nv_bfloat16 h = __float2bfloat16(v);
        __nv_bfloat16 l = __float2bfloat16(v - __bfloat162float(h));
        g_whi[(size_t)n * DDIM + k0 + tx] = h;
        g_wlo[(size_t)n * DDIM + k0 + tx] = l;
    }
}

// ---------------------------------------------------------------------------
// Projection GEMM, bf16x3 HMMA: out = X@W + b (fp32-accurate via hi/lo split)
// 128x128 tile, BK=64, cp.async double-buffered, SW128 swizzle.
// ---------------------------------------------------------------------------
#define PT (128 * 128)               // 16KB: one tile (128 rows x 128B)
#define PSMEM_BYTES (8 * PT)         // 4 tiles x 2 stages = 128KB

__device__ __forceinline__ void proj_load_stage(uint32_t ss, size_t m_base,
                                                int bn, int kc, int tid) {
#pragma unroll
    for (int it = 0; it < 4; ++it) {
        int idx = it * 256 + tid;
        int r = idx >> 3, c = idx & 7;
        uint32_t so = SWZ(r * 128 + c * 16);
        const size_t ka = (m_base + r) * DDIM + kc * 64 + c * 8;
        const size_t kb = (size_t)(bn + r) * DDIM + kc * 64 + c * 8;
        asm volatile("cp.async.cg.shared.global [%0], [%1], 16;"
                     :: "r"(ss + so), "l"((const void*)&g_xhi[ka]));
        asm volatile("cp.async.cg.shared.global [%0], [%1], 16;"
                     :: "r"(ss + PT + so), "l"((const void*)&g_xlo[ka]));
        asm volatile("cp.async.cg.shared.global [%0], [%1], 16;"
                     :: "r"(ss + 2 * PT + so), "l"((const void*)&g_whi[kb]));
        asm volatile("cp.async.cg.shared.global [%0], [%1], 16;"
                     :: "r"(ss + 3 * PT + so), "l"((const void*)&g_wlo[kb]));
    }
}

__global__ __launch_bounds__(256, 1) void proj_mma_kernel(
    const float* __restrict__ bias, float* __restrict__ out)
{
    extern __shared__ __align__(1024) char smem[];
    const uint32_t sb = smem_u32(smem);
    const int tid = threadIdx.x;
    const int wid = tid >> 5, lane = tid & 31;
    const int z = blockIdx.z;
    const int bm = blockIdx.y * 128;
    const int bn = blockIdx.x * 128;
    const size_t m_base = (size_t)z * NB + bm;
    const int coloff = z ? DDIM : 0;
    __nv_bfloat16* bf = z ? g_pbf : g_abf;
    const int m_off = (wid & 3) * 32;
    const int n_off = (wid >> 2) * 64;

    const uint32_t stage[2] = {sb, sb + 4 * PT};

    float acc[2][8][4];
#pragma unroll
    for (int i = 0; i < 2; ++i)
#pragma unroll
        for (int j = 0; j < 8; ++j)
#pragma unroll
            for (int c = 0; c < 4; ++c) acc[i][j][c] = 0.f;

    proj_load_stage(stage[0], m_base, bn, 0, tid);
    asm volatile("cp.async.commit_group;" ::: "memory");

    const int mi = lane >> 3;
    const int mr = lane & 7;

    for (int kc = 0; kc < DDIM / 64; ++kc) {
        const int cur = kc & 1;
        if (kc + 1 < DDIM / 64) {
            proj_load_stage(stage[cur ^ 1], m_base, bn, kc + 1, tid);
            asm volatile("cp.async.commit_group;" ::: "memory");
            asm volatile("cp.async.wait_group 1;" ::: "memory");
        } else {
            asm volatile("cp.async.wait_group 0;" ::: "memory");
        }
        __syncthreads();
        const uint32_t sAh = stage[cur], sAl = stage[cur] + PT;
        const uint32_t sBh = stage[cur] + 2 * PT, sBl = stage[cur] + 3 * PT;

#pragma unroll
        for (int ks = 0; ks < 4; ++ks) {
            const int arow0 = m_off + ((mi & 1) << 3) + mr;
            const int akb = ks * 32 + ((mi >> 1) << 4);
            uint32_t ah[2][4], al[2][4];
#pragma unroll
            for (int i = 0; i < 2; ++i) {
                uint32_t off = SWZ((arow0 + i * 16) * 128 + akb);
                asm volatile(
                    "ldmatrix.sync.aligned.m8n8.x4.shared.b16 {%0,%1,%2,%3}, [%4];"
                    : "=r"(ah[i][0]), "=r"(ah[i][1]), "=r"(ah[i][2]), "=r"(ah[i][3])
                    : "r"(sAh + off));
                asm volatile(
                    "ldmatrix.sync.aligned.m8n8.x4.shared.b16 {%0,%1,%2,%3}, [%4];"
                    : "=r"(al[i][0]), "=r"(al[i][1]), "=r"(al[i][2]), "=r"(al[i][3])
                    : "r"(sAl + off));
            }
            uint32_t bh[4][4], bl[4][4];
            const int brow0 = n_off + ((mi >> 1) << 3) + mr;
            const int bkb = ks * 32 + ((mi & 1) << 4);
#pragma unroll
            for (int j2 = 0; j2 < 4; ++j2) {
                uint32_t off = SWZ((brow0 + j2 * 16) * 128 + bkb);
                asm volatile(
                    "ldmatrix.sync.aligned.m8n8.x4.shared.b16 {%0,%1,%2,%3}, [%4];"
                    : "=r"(bh[j2][0]), "=r"(bh[j2][1]), "=r"(bh[j2][2]), "=r"(bh[j2][3])
                    : "r"(sBh + off));
                asm volatile(
                    "ldmatrix.sync.aligned.m8n8.x4.shared.b16 {%0,%1,%2,%3}, [%4];"
                    : "=r"(bl[j2][0]), "=r"(bl[j2][1]), "=r"(bl[j2][2]), "=r"(bl[j2][3])
                    : "r"(sBl + off));
            }
#pragma unroll
            for (int i = 0; i < 2; ++i)
#pragma unroll
                for (int j = 0; j < 8; ++j) {
                    const int q = j >> 1, s = (j & 1) * 2;
#define PROJ_MMA(AF, B0, B1)                                                   \
    asm volatile(                                                              \
        "mma.sync.aligned.m16n8k16.row.col.f32.bf16.bf16.f32 "                 \
        "{%0,%1,%2,%3}, {%4,%5,%6,%7}, {%8,%9}, {%0,%1,%2,%3};"                \
        : "+f"(acc[i][j][0]), "+f"(acc[i][j][1]),                              \
          "+f"(acc[i][j][2]), "+f"(acc[i][j][3])                               \
        : "r"(AF[i][0]), "r"(AF[i][1]), "r"(AF[i][2]), "r"(AF[i][3]),          \
          "r"(B0), "r"(B1))
                    PROJ_MMA(ah, bh[q][s], bh[q][s + 1]);
                    PROJ_MMA(ah, bl[q][s], bl[q][s + 1]);
                    PROJ_MMA(al, bh[q][s], bh[q][s + 1]);
#undef PROJ_MMA
                }
        }
        __syncthreads();
    }

    // epilogue: add bias, write fp32 out + bf16 copies
    const int g = lane >> 2;
    const int c2 = (lane & 3) * 2;
#pragma unroll
    for (int i = 0; i < 2; ++i) {
#pragma unroll
        for (int j = 0; j < 8; ++j) {
            const int ncol = bn + n_off + j * 8 + c2;
            const float b0 = bias[ncol], b1 = bias[ncol + 1];
            const int r0 = bm + m_off + i * 16 + g;
            const int r1 = r0 + 8;
            float v00 = acc[i][j][0] + b0, v01 = acc[i][j][1] + b1;
            float v10 = acc[i][j][2] + b0, v11 = acc[i][j][3] + b1;
            *reinterpret_cast<float2*>(&out[(size_t)r0 * OLD + coloff + ncol]) =
                make_float2(v00, v01);
            *reinterpret_cast<float2*>(&out[(size_t)r1 * OLD + coloff + ncol]) =
                make_float2(v10, v11);
            __nv_bfloat162 c0 = __floats2bfloat162_rn(v00, v01);
            __nv_bfloat162 c1 = __floats2bfloat162_rn(v10, v11);
            *reinterpret_cast<uint32_t*>(&bf[(size_t)r0 * DDIM + ncol]) =
                *reinterpret_cast<uint32_t*>(&c0);
            *reinterpret_cast<uint32_t*>(&bf[(size_t)r1 * DDIM + ncol]) =
                *reinterpret_cast<uint32_t*>(&c1);
        }
    }
}

// ---------------------------------------------------------------------------
// ||pos_row||^2
// ---------------------------------------------------------------------------
__global__ __launch_bounds__(256) void norms_kernel(const float* __restrict__ out) {
    const int row = blockIdx.x;
    const float4* p = reinterpret_cast<const float4*>(out + (size_t)row * OLD + DDIM);
    float4 v = p[threadIdx.x];
    float s = v.x * v.x + v.y * v.y + v.z * v.z + v.w * v.w;
#pragma unroll
    for (int off = 16; off > 0; off >>= 1) s += __shfl_down_sync(0xFFFFFFFFu, s, off);
    __shared__ float ws[8];
    const int lane = threadIdx.x & 31, warp = threadIdx.x >> 5;
    if (lane == 0) ws[warp] = s;
    __syncthreads();
    if (threadIdx.x == 0) {
        float t = 0.f;
#pragma unroll
        for (int w = 0; w < 8; ++w) t += ws[w];
        g_p2[row] = t;
    }
}

// ---------------------------------------------------------------------------
// Phase 1: bf16 mma.sync dist estimate -> half est matrix
// ---------------------------------------------------------------------------
#define TILE_BYTES (128 * 128)
#define DSMEM_BYTES (4 * TILE_BYTES)

__device__ __forceinline__ void load_stage(uint32_t sA, uint32_t sB,
                                           int bm, int bn, int kc, int tid) {
#pragma unroll
    for (int it = 0; it < 4; ++it) {
        int idx = it * 256 + tid;
        int r = idx >> 3, c = idx & 7;
        uint32_t so = SWZ(r * 128 + c * 16);
        asm volatile("cp.async.cg.shared.global [%0], [%1], 16;"
                     :: "r"(sA + so),
                        "l"((const void*)&g_abf[(size_t)(bm + r) * DDIM + kc * 64 + c * 8]));
        asm volatile("cp.async.cg.shared.global [%0], [%1], 16;"
                     :: "r"(sB + so),
                        "l"((const void*)&g_pbf[(size_t)(bn + r) * DDIM + kc * 64 + c * 8]));
    }
}

__global__ __launch_bounds__(256) void dist_est_kernel() {
    extern __shared__ __align__(1024) char smem[];
    const uint32_t sb = smem_u32(smem);
    const int tid = threadIdx.x;
    const int wid = tid >> 5, lane = tid & 31;
    const int bm = blockIdx.y * 128;
    const int bn = blockIdx.x * 128;
    const int m_off = (wid & 3) * 32;
    const int n_off = (wid >> 2) * 64;

    const uint32_t sA[2] = {sb,              sb + 2 * TILE_BYTES};
    const uint32_t sB[2] = {sb + TILE_BYTES, sb + 3 * TILE_BYTES};

    float acc[2][8][4];
#pragma unroll
    for (int i = 0; i < 2; ++i)
#pragma unroll
        for (int j = 0; j < 8; ++j)
#pragma unroll
            for (int c = 0; c < 4; ++c) acc[i][j][c] = 0.f;

    load_stage(sA[0], sB[0], bm, bn, 0, tid);
    asm volatile("cp.async.commit_group;" ::: "memory");

    const int mi = lane >> 3;
    const int mr = lane & 7;

    for (int kc = 0; kc < DDIM / 64; ++kc) {
        const int cur = kc & 1;
        if (kc + 1 < DDIM / 64) {
            load_stage(sA[cur ^ 1], sB[cur ^ 1], bm, bn, kc + 1, tid);
            asm volatile("cp.async.commit_group;" ::: "memory");
            asm volatile("cp.async.wait_group 1;" ::: "memory");
        } else {
            asm volatile("cp.async.wait_group 0;" ::: "memory");
        }
        __syncthreads();

#pragma unroll
        for (int ks = 0; ks < 4; ++ks) {
            uint32_t a[2][4];
#pragma unroll
            for (int i = 0; i < 2; ++i) {
                int row = m_off + i * 16 + ((mi & 1) << 3) + mr;
                int kb = ks * 32 + ((mi >> 1) << 4);
                asm volatile(
                    "ldmatrix.sync.aligned.m8n8.x4.shared.b16 {%0,%1,%2,%3}, [%4];"
                    : "=r"(a[i][0]), "=r"(a[i][1]), "=r"(a[i][2]), "=r"(a[i][3])
                    : "r"(sA[cur] + SWZ(row * 128 + kb)));
            }
            uint32_t b[4][4];
#pragma unroll
            for (int j2 = 0; j2 < 4; ++j2) {
                int row = n_off + j2 * 16 + ((mi >> 1) << 3) + mr;
                int kb = ks * 32 + ((mi & 1) << 4);
                asm volatile(
                    "ldmatrix.sync.aligned.m8n8.x4.shared.b16 {%0,%1,%2,%3}, [%4];"
                    : "=r"(b[j2][0]), "=r"(b[j2][1]), "=r"(b[j2][2]), "=r"(b[j2][3])
                    : "r"(sB[cur] + SWZ(row * 128 + kb)));
            }
#pragma unroll
            for (int i = 0; i < 2; ++i)
#pragma unroll
                for (int j = 0; j < 8; ++j) {
                    const uint32_t b0 = b[j >> 1][(j & 1) * 2];
                    const uint32_t b1 = b[j >> 1][(j & 1) * 2 + 1];
                    asm volatile(
                        "mma.sync.aligned.m16n8k16.row.col.f32.bf16.bf16.f32 "
                        "{%0,%1,%2,%3}, {%4,%5,%6,%7}, {%8,%9}, {%0,%1,%2,%3};"
                        : "+f"(acc[i][j][0]), "+f"(acc[i][j][1]),
                          "+f"(acc[i][j][2]), "+f"(acc[i][j][3])
                        : "r"(a[i][0]), "r"(a[i][1]), "r"(a[i][2]), "r"(a[i][3]),
                          "r"(b0), "r"(b1));
                }
        }
        __syncthreads();
    }

    const int g = lane >> 2;
    const int c2 = (lane & 3) * 2;
#pragma unroll
    for (int i = 0; i < 2; ++i) {
#pragma unroll
        for (int j = 0; j < 8; ++j) {
            const int ncol = bn + n_off + j * 8 + c2;
            const float p2a = g_p2[ncol];
            const float p2b = g_p2[ncol + 1];
            const int r0 = bm + m_off + i * 16 + g;
            const int r1 = r0 + 8;
            float e00 = fmaf(-2.f, acc[i][j][0], p2a);
            float e01 = fmaf(-2.f, acc[i][j][1], p2b);
            float e10 = fmaf(-2.f, acc[i][j][2], p2a);
            float e11 = fmaf(-2.f, acc[i][j][3], p2b);
            if (ncol == r0) e00 = 65504.f;
            if (ncol + 1 == r0) e01 = 65504.f;
            if (ncol == r1) e10 = 65504.f;
            if (ncol + 1 == r1) e11 = 65504.f;
            *reinterpret_cast<__half2*>(&g_est[(size_t)r0 * NB + ncol]) =
                __floats2half2_rn(e00, e01);
            *reinterpret_cast<__half2*>(&g_est[(size_t)r1 * NB + ncol]) =
                __floats2half2_rn(e10, e11);
        }
    }
}

// ---------------------------------------------------------------------------
// Phase 2: per-row refine — exact fp32 distance on candidates within MARGIN.
// ---------------------------------------------------------------------------
#define MARGIN 6.0f

__global__ __launch_bounds__(256) void refine_kernel(const float* __restrict__ out) {
    const int row = blockIdx.x;
    const int tid = threadIdx.x;
    const int wid = tid >> 5, lid = tid & 31;
    const __half2* e2 =
        reinterpret_cast<const __half2*>(&g_est[(size_t)row * NB]);

    __shared__ float red[8];
    __shared__ int   cand[64];
    __shared__ int   ccount;
    __shared__ float arow[DDIM];

    float2 f[8];
#pragma unroll
    for (int it = 0; it < 8; ++it) f[it] = __half22float2(e2[it * 256 + tid]);
    float lmin = 3.0e38f;
#pragma unroll
    for (int it = 0; it < 8; ++it) lmin = fminf(lmin, fminf(f[it].x, f[it].y));
#pragma unroll
    for (int off = 16; off > 0; off >>= 1)
        lmin = fminf(lmin, __shfl_xor_sync(0xFFFFFFFFu, lmin, off));
    if (lid == 0) red[wid] = lmin;
    if (tid == 0) ccount = 0;
    __syncthreads();
    float rowmin = red[0];
#pragma unroll
    for (int w = 1; w < 8; ++w) rowmin = fminf(rowmin, red[w]);

    const float thr = rowmin + MARGIN;
#pragma unroll
    for (int it = 0; it < 8; ++it) {
        const int j = (it * 256 + tid) * 2;
        if (f[it].x <= thr && j != row) {
            int p = atomicAdd(&ccount, 1);
            if (p < 64) cand[p] = j;
        }
        if (f[it].y <= thr && j + 1 != row) {
            int p = atomicAdd(&ccount, 1);
            if (p < 64) cand[p] = j + 1;
        }
    }
    for (int j = tid; j < DDIM; j += 256) arow[j] = out[(size_t)row * OLD + j];
    __syncthreads();

    int nc = ccount; if (nc > 64) nc = 64;
    unsigned long long best = ~0ull;
    for (int k = 0; k < nc; ++k) {
        const int j = cand[k];
        const float* prow = &out[(size_t)j * OLD + DDIM];
        float s = 0.f;
        for (int t = tid; t < DDIM; t += 256) s = fmaf(arow[t], prow[t], s);
#pragma unroll
        for (int off = 16; off > 0; off >>= 1) s += __shfl_xor_sync(0xFFFFFFFFu, s, off);
        if (lid == 0) red[wid] = s;
        __syncthreads();
        if (tid == 0) {
            float dot = 0.f;
#pragma unroll
            for (int w = 0; w < 8; ++w) dot += red[w];
            float dist = fmaf(-2.0f, dot, g_p2[j]);
            unsigned long long pk =
                ((unsigned long long)__float_as_uint(dist) << 32) | (unsigned)j;
            if (pk < best) best = pk;
        }
        __syncthreads();
    }
    if (tid == 0) g_idx[row] = (int)(unsigned)(best & 0xFFFFFFFFull);
}

// ---------------------------------------------------------------------------
// Gather hard negatives: out[:, 2048:3072] = pos[argmin]
// ---------------------------------------------------------------------------
__global__ __launch_bounds__(256) void gather_kernel(float* __restrict__ out) {
    const int row = blockIdx.x;
    const int idx = g_idx[row];
    const float4* src = reinterpret_cast<const float4*>(out + (size_t)idx * OLD + DDIM);
    float4* dst = reinterpret_cast<float4*>(out + (size_t)row * OLD + 2 * DDIM);
    dst[threadIdx.x] = src[threadIdx.x];
}

// ---------------------------------------------------------------------------
extern "C" void kernel_launch(void* const* d_in, const int* in_sizes, int n_in,
                              void* d_out, int out_size) {
    (void)in_sizes; (void)n_in; (void)out_size;
    const float* ax   = (const float*)d_in[0];
    const float* px   = (const float*)d_in[1];
    const float* W    = (const float*)d_in[2];
    const float* bias = (const float*)d_in[3];
    float* out = (float*)d_out;

    cudaFuncSetAttribute(proj_mma_kernel,
                         cudaFuncAttributeMaxDynamicSharedMemorySize, PSMEM_BYTES);
    cudaFuncSetAttribute(dist_est_kernel,
                         cudaFuncAttributeMaxDynamicSharedMemorySize, DSMEM_BYTES);

    split_x_kernel<<<dim3(NB * DDIM / (256 * 8), 2), 256>>>(ax, px);
    split_w_kernel<<<dim3(DDIM / 32, DDIM / 32), 256>>>(W);
    proj_mma_kernel<<<dim3(DDIM / 128, NB / 128, 2), 256, PSMEM_BYTES>>>(bias, out);
    norms_kernel<<<NB, 256>>>(out);
    dist_est_kernel<<<dim3(NB / 128, NB / 128), 256, DSMEM_BYTES>>>();
    refine_kernel<<<NB, 256>>>(out);
    gather_kernel<<<NB, 256>>>(out);
}